// round 16
// baseline (speedup 1.0000x reference)
#include <cuda_runtime.h>
#include <cuda_fp16.h>
#include <math.h>
#include <stdint.h>

// Problem constants (fixed shapes)
#define B_  8
#define N_  4096
#define C_  256
#define K_  4
#define NK_ (N_ * K_)

#define BM 128
#define BN 64
#define THREADS 256
#define NBLK   32                 // N / 128 row blocks
#define NPAIR  528                // NBLK*(NBLK+1)/2 unordered pairs
#define CHUNKS 8                  // C / 32 k-chunks (full K per CTA)

// smem rows: 16 pairs as 8 x 16B units = 128B data, padded to 192B.
// Stride 48 words == 16 banks (mod 32): conflict-free LDS.128 fragments
// (verified round 14).
#define ROW_BYTES   192
#define A_BYTES     (BM * ROW_BYTES)          // 24576
#define B_BYTES     (BN * ROW_BYTES)          // 12288
#define STAGE_BYTES (A_BYTES + B_BYTES)       // 36864
#define SMEM_TOTAL  (2 * STAGE_BYTES)         // 73728 (x2 CTAs = 147456)

// Packed fp16 hi/lo split, FRAGMENT-ORDER layout (verified round 14).
__device__ uint2 g_pack[(size_t)B_ * N_ * (C_ / 2)];

// Top-4 partial lists, SLOT-MAJOR for coalesced merge reads:
//   g_part[slot][b][n][4] = (value, index), slot in [0, 96).
// Node n (block Ib = n>>7) is written at:
//   row-partials: slot = 2*J + half, J >= Ib        -> [2*Ib, 64)
//   col-partials: slot = 64 + I,     I <  Ib        -> [64, 64+Ib)
// Exactly covering, no overlap, no uninitialized slot is ever read.
#define NSLOT 96
__device__ float2 g_part[(size_t)NSLOT * B_ * N_ * K_];

// ---------------------------------------------------------------------------
__device__ __forceinline__ uint2 pack_pair(float a, float b) {
    __half ha = __float2half_rn(a);
    __half hb = __float2half_rn(b);
    __half la = __float2half_rn(a - __half2float(ha));
    __half lb = __float2half_rn(b - __half2float(hb));
    uint2 r;
    r.x = (uint32_t)__half_as_ushort(ha) | ((uint32_t)__half_as_ushort(hb) << 16);
    r.y = (uint32_t)__half_as_ushort(la) | ((uint32_t)__half_as_ushort(lb) << 16);
    return r;
}

__device__ __forceinline__ void store_pair(uint32_t* o, int p, float a, float b) {
    uint2 v = pack_pair(a, b);
    int t = p >> 4, r = p & 15;
    int h = r >> 3, j = r & 7;
    int u = 4 * h + (j & 3);
    int slot = j >> 2;
    int wi = t * 32 + u * 4 + slot;
    o[wi]     = v.x;
    o[wi + 2] = v.y;
}

// Kernel 1: row-wise L2 normalize + fp16 hi/lo split + fragment-order pack.
__global__ void normalize_kernel(const float* __restrict__ x) {
    int row  = blockIdx.x * 8 + (threadIdx.x >> 5);
    int lane = threadIdx.x & 31;
    const float4* r = (const float4*)(x + (size_t)row * C_);
    float4 v0 = r[lane];
    float4 v1 = r[lane + 32];
    float s = v0.x * v0.x + v0.y * v0.y + v0.z * v0.z + v0.w * v0.w
            + v1.x * v1.x + v1.y * v1.y + v1.z * v1.z + v1.w * v1.w;
#pragma unroll
    for (int off = 16; off; off >>= 1)
        s += __shfl_xor_sync(0xffffffffu, s, off);
    float nrm = sqrtf(s);
    uint32_t* o = (uint32_t*)(g_pack + (size_t)row * (C_ / 2));
    store_pair(o, 2 * lane + 0,  v0.x / nrm, v0.y / nrm);
    store_pair(o, 2 * lane + 1,  v0.z / nrm, v0.w / nrm);
    store_pair(o, 64 + 2 * lane + 0, v1.x / nrm, v1.y / nrm);
    store_pair(o, 64 + 2 * lane + 1, v1.z / nrm, v1.w / nrm);
}

// ---------------------------------------------------------------------------
__device__ __forceinline__ void cp16(uint32_t dst, const void* src) {
    asm volatile("cp.async.ca.shared.global [%0], [%1], 16;\n"
                 :: "r"(dst), "l"(src));
}
__device__ __forceinline__ void cp_commit() {
    asm volatile("cp.async.commit_group;\n");
}
__device__ __forceinline__ void mma_f16(float* c, const uint32_t* a,
                                        uint32_t b0, uint32_t b1) {
    asm volatile(
        "mma.sync.aligned.m16n8k16.row.col.f32.f16.f16.f32 "
        "{%0,%1,%2,%3}, {%4,%5,%6,%7}, {%8,%9}, {%0,%1,%2,%3};\n"
        : "+f"(c[0]), "+f"(c[1]), "+f"(c[2]), "+f"(c[3])
        : "r"(a[0]), "r"(a[1]), "r"(a[2]), "r"(a[3]), "r"(b0), "r"(b1));
}

// ---------------------------------------------------------------------------
// Kernel 2: SYMMETRIC fused fp16-3x tensor-core sim-GEMM + dual-direction
// top-4 fold. One CTA per (unordered block pair {I,J}) x (column half):
// tile = rows of block I (128) x 64 cols of block J. Each entry computed
// ONCE; folded into row-partials (block I) and, for I != J, col-partials
// (block J) via a warp-shuffle + smem transpose reduce. 51.6% of the HMMA
// work of the full N x N sweep. Compute body verbatim from round 14.
// ---------------------------------------------------------------------------
__global__ __launch_bounds__(THREADS, 2)
void knn_kernel() {
    extern __shared__ char smem_raw[];
    const int b = blockIdx.y;
    // unrank blockIdx.x -> (pair index, half) -> (I, J)
    int t = blockIdx.x >> 1;
    const int half = blockIdx.x & 1;
    int I = 0;
#pragma unroll 1
    while (t >= NBLK - I) { t -= NBLK - I; I++; }
    const int J = I + t;
    const int RI    = I * BM;                  // tile row base
    const int cbase = J * BM + half * BN;      // tile col base
    const uint2* __restrict__ fb = g_pack + (size_t)b * N_ * (C_ / 2);

    const int tid  = threadIdx.x;
    const int warp = tid >> 5;
    const int lane = tid & 31;
    const int gid  = lane >> 2;
    const int tq   = lane & 3;
    const int m0   = warp * 16;

    const uint32_t sbase = (uint32_t)__cvta_generic_to_shared(smem_raw);
    const int lr = tid >> 3;
    const int lc = tid & 7;

    float acc[32];
#pragma unroll
    for (int j = 0; j < 32; j++) acc[j] = 0.0f;

#define LOAD_CHUNK(q)                                                           \
    do {                                                                        \
        const int _pp = (q) * 16;                                               \
        const uint32_t _sA = sbase + ((q) & 1) * STAGE_BYTES;                   \
        const uint32_t _sB = _sA + A_BYTES;                                     \
        _Pragma("unroll")                                                       \
        for (int i = 0; i < 4; i++) {                                           \
            int r = lr + i * 32;                                                \
            cp16(_sA + r * ROW_BYTES + lc * 16,                                 \
                 fb + (size_t)(RI + r) * (C_ / 2) + _pp + lc * 2);              \
        }                                                                       \
        _Pragma("unroll")                                                       \
        for (int i = 0; i < 2; i++) {                                           \
            int r = lr + i * 32;                                                \
            cp16(_sB + r * ROW_BYTES + lc * 16,                                 \
                 fb + (size_t)(cbase + r) * (C_ / 2) + _pp + lc * 2);           \
        }                                                                       \
        cp_commit();                                                            \
    } while (0)

    LOAD_CHUNK(0);
    for (int q = 0; q < CHUNKS; q++) {
        asm volatile("cp.async.wait_group 0;\n" ::: "memory");
        __syncthreads();
        if (q + 1 < CHUNKS)
            LOAD_CHUNK(q + 1);

        const char* pA = smem_raw + (q & 1) * STAGE_BYTES;
        const char* pB = pA + A_BYTES;
#pragma unroll
        for (int h = 0; h < 2; h++) {
            const int uoff = (4 * h + tq) * 16;
            const char* abase = pA + (m0 + gid) * ROW_BYTES + uoff;
            uint4 q0 = *(const uint4*)abase;
            uint4 q1 = *(const uint4*)(abase + 8 * ROW_BYTES);
            uint32_t ahi[4] = { q0.x, q1.x, q0.y, q1.y };
            uint32_t alo[4] = { q0.z, q1.z, q0.w, q1.w };
#pragma unroll
            for (int nt = 0; nt < 8; nt++) {
                uint4 v = *(const uint4*)(pB + (nt * 8 + gid) * ROW_BYTES + uoff);
                float* c = acc + nt * 4;
                mma_f16(c, ahi, v.x, v.y);   // hi*hi
                mma_f16(c, ahi, v.z, v.w);   // hi*lo
                mma_f16(c, alo, v.x, v.y);   // lo*hi
            }
        }
    }
#undef LOAD_CHUNK

    // ================= ROW-direction fold (rows of block I) ================
    float topv[2][4];
    int   topi[2][4];
#pragma unroll
    for (int i = 0; i < 2; i++)
#pragma unroll
        for (int s = 0; s < 4; s++) { topv[i][s] = -INFINITY; topi[i][s] = 0x7fffffff; }

#pragma unroll
    for (int i = 0; i < 2; i++) {
        const int g = RI + m0 + gid + i * 8;
#pragma unroll
        for (int nt = 0; nt < 8; nt++) {
#pragma unroll
            for (int j = 0; j < 2; j++) {
                int   col = cbase + nt * 8 + 2 * tq + j;
                float v   = acc[nt * 4 + i * 2 + j];
                if (col != g && v > topv[i][3]) {
                    if (v > topv[i][0]) {
                        topv[i][3] = topv[i][2]; topi[i][3] = topi[i][2];
                        topv[i][2] = topv[i][1]; topi[i][2] = topi[i][1];
                        topv[i][1] = topv[i][0]; topi[i][1] = topi[i][0];
                        topv[i][0] = v;          topi[i][0] = col;
                    } else if (v > topv[i][1]) {
                        topv[i][3] = topv[i][2]; topi[i][3] = topi[i][2];
                        topv[i][2] = topv[i][1]; topi[i][2] = topi[i][1];
                        topv[i][1] = v;          topi[i][1] = col;
                    } else if (v > topv[i][2]) {
                        topv[i][3] = topv[i][2]; topi[i][3] = topi[i][2];
                        topv[i][2] = v;          topi[i][2] = col;
                    } else {
                        topv[i][3] = v;          topi[i][3] = col;
                    }
                }
            }
        }
    }

    // quad merge (4 lanes share each row) and write row-partial slot 2J+half
    const int slotR = 2 * J + half;
#pragma unroll
    for (int i = 0; i < 2; i++) {
        const int g = RI + m0 + gid + i * 8;
        float2* dst = g_part + (((size_t)slotR * B_ + b) * N_ + g) * K_;
        int p = 0;
#pragma unroll
        for (int s = 0; s < 4; s++) {
            float cv = (p < 4) ? topv[i][p] : -INFINITY;
            int   ci = (p < 4) ? topi[i][p] : 0x7fffffff;
#pragma unroll
            for (int off = 1; off <= 2; off <<= 1) {
                float ov = __shfl_xor_sync(0xffffffffu, cv, off);
                int   oi = __shfl_xor_sync(0xffffffffu, ci, off);
                if (ov > cv || (ov == cv && oi < ci)) { cv = ov; ci = oi; }
            }
            if (p < 4 && topi[i][p] == ci) p++;
            if (tq == s) dst[s] = make_float2(cv, (float)ci);
        }
    }

    // ================= COL-direction fold (cols of block J) ================
    if (I != J) {
        __syncthreads();   // stage buffers dead -> reuse as partial scratch
        float2* sPart = (float2*)smem_raw;   // [col 64][warp 8][slot 4]
#pragma unroll
        for (int nt = 0; nt < 8; nt++) {
#pragma unroll
            for (int j = 0; j < 2; j++) {
                const int c = nt * 8 + 2 * tq + j;
                float a0 = acc[nt * 4 + 0 * 2 + j];
                float a1 = acc[nt * 4 + 1 * 2 + j];
                int   i0 = RI + m0 + gid, i1 = i0 + 8;
                float h0 = a0, h1 = a1; int hi0 = i0, hi1 = i1;
                if (a1 > a0) { h0 = a1; hi0 = i1; h1 = a0; hi1 = i0; }
                int p = 0;
#pragma unroll
                for (int s = 0; s < 4; s++) {
                    float cv = (p == 0) ? h0 : ((p == 1) ? h1 : -INFINITY);
                    int   ci = (p == 0) ? hi0 : ((p == 1) ? hi1 : 0x7fffffff);
#pragma unroll
                    for (int off = 4; off <= 16; off <<= 1) {
                        float ov = __shfl_xor_sync(0xffffffffu, cv, off);
                        int   oi = __shfl_xor_sync(0xffffffffu, ci, off);
                        if (ov > cv || (ov == cv && oi < ci)) { cv = ov; ci = oi; }
                    }
                    int myhead = (p == 0) ? hi0 : ((p == 1) ? hi1 : 0x7fffffff);
                    if (p < 2 && myhead == ci) p++;
                    if (gid == 0)
                        sPart[(c * 8 + warp) * 4 + s] = make_float2(cv, (float)ci);
                }
            }
        }
        __syncthreads();
        if (tid < 64) {
            const int c = tid;
            float tv[4] = { -INFINITY, -INFINITY, -INFINITY, -INFINITY };
            int   ti[4] = { 0x7fffffff, 0x7fffffff, 0x7fffffff, 0x7fffffff };
#pragma unroll
            for (int w = 0; w < 8; w++) {
                const float2* l = &sPart[(c * 8 + w) * 4];
                for (int e = 0; e < 4; e++) {
                    float v  = l[e].x;
                    int   ii = (int)l[e].y;
                    bool bet3 = (v > tv[3]) || (v == tv[3] && ii < ti[3]);
                    if (!bet3) break;    // list sorted -> rest worse
                    if (v > tv[0] || (v == tv[0] && ii < ti[0])) {
                        tv[3]=tv[2]; ti[3]=ti[2]; tv[2]=tv[1]; ti[2]=ti[1];
                        tv[1]=tv[0]; ti[1]=ti[0]; tv[0]=v; ti[0]=ii;
                    } else if (v > tv[1] || (v == tv[1] && ii < ti[1])) {
                        tv[3]=tv[2]; ti[3]=ti[2]; tv[2]=tv[1]; ti[2]=ti[1];
                        tv[1]=v; ti[1]=ii;
                    } else if (v > tv[2] || (v == tv[2] && ii < ti[2])) {
                        tv[3]=tv[2]; ti[3]=ti[2]; tv[2]=v; ti[2]=ii;
                    } else {
                        tv[3]=v; ti[3]=ii;
                    }
                }
            }
            const int node = cbase + c;
            float2* dst = g_part + (((size_t)(64 + I) * B_ + b) * N_ + node) * K_;
#pragma unroll
            for (int s = 0; s < 4; s++)
                dst[s] = make_float2(tv[s], (float)ti[s]);
        }
    }
}

// ---------------------------------------------------------------------------
// Kernel 3: merge each node's partial lists, emit edges.
// Node n (block Ib = n>>7) reads slots [2*Ib, 64) and [64, 64+Ib).
// Output layout (float32):
//   [b*2*NK .. ]        : src indices
//   [b*2*NK + NK .. ]   : tgt indices
//   [B*2*NK + b*NK .. ] : weights
// ---------------------------------------------------------------------------
__global__ void merge_kernel(float* __restrict__ out) {
    int idx = blockIdx.x * 256 + threadIdx.x;   // 0 .. B*N-1
    int b = idx >> 12, n = idx & (N_ - 1);
    const int Ib = n >> 7;

    float tv[4] = { -INFINITY, -INFINITY, -INFINITY, -INFINITY };
    int   ti[4] = { 0x7fffffff, 0x7fffffff, 0x7fffffff, 0x7fffffff };

    for (int phase = 0; phase < 2; phase++) {
        int s0 = phase ? 64 : 2 * Ib;
        int s1 = phase ? 64 + Ib : 64;
        for (int slot = s0; slot < s1; slot++) {
            const float2* l = g_part + (((size_t)slot * B_ + b) * N_ + n) * K_;
            for (int e = 0; e < 4; e++) {
                float v  = l[e].x;
                int   ii = (int)l[e].y;
                bool bet3 = (v > tv[3]) || (v == tv[3] && ii < ti[3]);
                if (!bet3) break;
                if (v > tv[0] || (v == tv[0] && ii < ti[0])) {
                    tv[3]=tv[2]; ti[3]=ti[2]; tv[2]=tv[1]; ti[2]=ti[1];
                    tv[1]=tv[0]; ti[1]=ti[0]; tv[0]=v; ti[0]=ii;
                } else if (v > tv[1] || (v == tv[1] && ii < ti[1])) {
                    tv[3]=tv[2]; ti[3]=ti[2]; tv[2]=tv[1]; ti[2]=ti[1];
                    tv[1]=v; ti[1]=ii;
                } else if (v > tv[2] || (v == tv[2] && ii < ti[2])) {
                    tv[3]=tv[2]; ti[3]=ti[2]; tv[2]=v; ti[2]=ii;
                } else {
                    tv[3]=v; ti[3]=ii;
                }
            }
        }
    }

    const size_t ibase = (size_t)b * 2 * NK_;
    const size_t wbase = (size_t)B_ * 2 * NK_ + (size_t)b * NK_;
#pragma unroll
    for (int s = 0; s < 4; s++) {
        out[ibase + (size_t)n * K_ + s]       = (float)n;
        out[ibase + NK_ + (size_t)n * K_ + s] = (float)ti[s];
        out[wbase + (size_t)n * K_ + s]       = tv[s];
    }
}

// ---------------------------------------------------------------------------
extern "C" void kernel_launch(void* const* d_in, const int* in_sizes, int n_in,
                              void* d_out, int out_size) {
    (void)in_sizes; (void)n_in; (void)out_size;
    const float* x = (const float*)d_in[0];
    float* out = (float*)d_out;

    cudaFuncSetAttribute(knn_kernel,
                         cudaFuncAttributeMaxDynamicSharedMemorySize, SMEM_TOTAL);

    normalize_kernel<<<(B_ * N_) / 8, 256>>>(x);
    dim3 grid(NPAIR * 2, B_, 1);
    knn_kernel<<<grid, THREADS, SMEM_TOTAL>>>();
    merge_kernel<<<(B_ * N_) / 256, 256>>>(out);
}